// round 15
// baseline (speedup 1.0000x reference)
#include <cuda_runtime.h>
#include <cuda_bf16.h>

// NDFT type-2, conjugate-pair symmetry over k1 (f_hat real):
//   pair +-t: f[t]e^{-ip} + f[-t]e^{+ip} = fs*cos(p) - i*fd*sin(p)
//   t=0: fs=f (fd row unused since sin(0)=0 -> we store fd=-f harmlessly);
//   t=32 (k1=-32 unpaired): fs=f, fd=-f; t=33: zero pad.
// Radix on k2: k2 = 16a + c - 32.
// Block: 256 thr = 8 warps = (a in [0,4), t-half h in [0,2)), 32 points.
// Lane = (p in [0,16), c-half ch in [0,2)); each lane owns points p and p+16.
// PLAIN SCALAR accumulation (no asm, no b64 packing -> no operand-marshaling
// MOVs); per-row twiddles via MUFU __sincosf (no loop-carried rotation chain).

#define B_DIM 2
#define M_DIM 8192
#define N1 64
#define N2 64
#define K_TOT (N1 * N2)
#define TPB 256
#define NWARP 8
#define PTS 32
#define BLOCKS_PER_B (M_DIM / PTS)           // 256
#define TROWS 34                             // t = 0..32 + zero pad
#define ROWS_PW 17

#define PI_F     3.14159265358979f
#define TWO_PI_F 6.28318530717959f

__global__ __launch_bounds__(TPB, 4) void ndft_kernel(
    const float* __restrict__ x,      // [B, M, 2]
    const float* __restrict__ f_hat,  // [B, 64, 64]
    float* __restrict__ out,
    const int real_only)
{
    __shared__ __align__(16) float sfd[TROWS * 128];  // (fs,fd) interleaved
    __shared__ float2 sy[16][PTS];                    // 16 partials per point

    const int b    = blockIdx.x / BLOCKS_PER_B;
    const int mblk = blockIdx.x % BLOCKS_PER_B;
    const int tid  = threadIdx.x;
    const int w    = tid >> 5;
    const int lane = tid & 31;
    const int a    = w & 3;                  // k2 radix digit
    const int h    = w >> 2;                 // t-half
    const int p    = lane & 15;              // first point; second = p + 16
    const int ch   = lane >> 4;              // c-half: c = 8*ch + j

    // ---- build fs/fd interleaved: sfd[t*128 + c64*2] = (fs, fd) ----
    {
        const float* fb = f_hat + b * K_TOT;
        for (int idx = tid; idx < TROWS * 16; idx += TPB) {
            const int t = idx >> 4;
            const int g = idx & 15;
            float4 fp = make_float4(0.f, 0.f, 0.f, 0.f);
            float4 fm = make_float4(0.f, 0.f, 0.f, 0.f);
            if (t >= 1 && t <= 31)
                fp = *reinterpret_cast<const float4*>(fb + (32 + t) * N2 + g * 4);
            if (t <= 32)
                fm = *reinterpret_cast<const float4*>(fb + (32 - t) * N2 + g * 4);
            float4* dst = reinterpret_cast<float4*>(sfd + t * 128 + g * 8);
            dst[0] = make_float4(fp.x + fm.x, fp.x - fm.x, fp.y + fm.y, fp.y - fm.y);
            dst[1] = make_float4(fp.z + fm.z, fp.z - fm.z, fp.w + fm.w, fp.w - fm.w);
        }
    }

    const int mbase = b * M_DIM + mblk * PTS;
    const float2 xv0 = reinterpret_cast<const float2*>(x)[mbase + p];
    const float2 xv1 = reinterpret_cast<const float2*>(x)[mbase + p + 16];
    __syncthreads();

    // per-row angle: ang_t = 2*pi*x1*t, t = 17h .. 17h+16
    const float d0 = TWO_PI_F * xv0.x;
    const float d1 = TWO_PI_F * xv1.x;
    float af0 = d0 * (float)(ROWS_PW * h);
    float af1 = d1 * (float)(ROWS_PW * h);

    // scalar accumulators (2 points x 8 local c's)
    float P0[8], Q0[8], P1[8], Q1[8];
    #pragma unroll
    for (int j = 0; j < 8; ++j) { P0[j] = Q0[j] = P1[j] = Q1[j] = 0.f; }

    // this lane's slice: 16 floats per row at offset a*32 + ch*16
    const float4* fsd = reinterpret_cast<const float4*>(
        sfd + (h * ROWS_PW) * 128 + a * 32 + ch * 16);

    #pragma unroll
    for (int t = 0; t < ROWS_PW; ++t) {
        float s0, c0, s1, c1;
        __sincosf(af0, &s0, &c0);
        __sincosf(af1, &s1, &c1);
        af0 += d0;
        af1 += d1;

        // (fs,fd) pairs: va = (fs0,fd0,fs1,fd1) for j=0,1 etc. Broadcast LDS.
        const float4 va = fsd[0];
        const float4 vb = fsd[1];
        const float4 vc = fsd[2];
        const float4 vd = fsd[3];

        P0[0] += va.x * c0;  Q0[0] += va.y * s0;
        P0[1] += va.z * c0;  Q0[1] += va.w * s0;
        P0[2] += vb.x * c0;  Q0[2] += vb.y * s0;
        P0[3] += vb.z * c0;  Q0[3] += vb.w * s0;
        P0[4] += vc.x * c0;  Q0[4] += vc.y * s0;
        P0[5] += vc.z * c0;  Q0[5] += vc.w * s0;
        P0[6] += vd.x * c0;  Q0[6] += vd.y * s0;
        P0[7] += vd.z * c0;  Q0[7] += vd.w * s0;

        P1[0] += va.x * c1;  Q1[0] += va.y * s1;
        P1[1] += va.z * c1;  Q1[1] += va.w * s1;
        P1[2] += vb.x * c1;  Q1[2] += vb.y * s1;
        P1[3] += vb.z * c1;  Q1[3] += vb.w * s1;
        P1[4] += vc.x * c1;  Q1[4] += vc.y * s1;
        P1[5] += vc.z * c1;  Q1[5] += vc.w * s1;
        P1[6] += vd.x * c1;  Q1[6] += vd.y * s1;
        P1[7] += vd.z * c1;  Q1[7] += vd.w * s1;

        fsd += 32;                     // next t row (128 floats)
    }

    // ---- tails (per point): T = sum_j w2^{8ch+j}(P_j - i Q_j); y = C_a*T ----
    #pragma unroll
    for (int k = 0; k < 2; ++k) {
        const float x2k = k ? xv1.y : xv0.y;
        const float* P = k ? P1 : P0;
        const float* Q = k ? Q1 : Q0;

        float w2r, w2i;                // w2 = cis(-2*pi*x2)
        __sincosf(-TWO_PI_F * x2k, &w2i, &w2r);
        float Cr, Ci;                  // C_a = cis(-2*pi*(16a-32)*x2)
        __sincosf((64.0f - 32.0f * (float)a) * PI_F * x2k, &Ci, &Cr);
        float fr, fi;                  // E2f anchor = cis(-2*pi*8*ch*x2)
        if (ch == 0) { fr = 1.0f; fi = 0.0f; }
        else        __sincosf(-16.0f * PI_F * x2k, &fi, &fr);

        float Tr = 0.0f, Ti = 0.0f;
        #pragma unroll
        for (int j = 0; j < 8; ++j) {
            Tr += fr * P[j] + fi * Q[j];
            Ti += fi * P[j] - fr * Q[j];
            const float tt = fr * w2r - fi * w2i;
            fi = fr * w2i + fi * w2r;
            fr = tt;
        }
        const float yr = Cr * Tr - Ci * Ti;
        const float yi = Cr * Ti + Ci * Tr;

        sy[w * 2 + ch][p + 16 * k] = make_float2(yr, yi);
    }
    __syncthreads();

    // ---- reduction: 16 partials per point ----
    if (tid < PTS) {
        float2 s = sy[0][tid];
        #pragma unroll
        for (int q = 1; q < 16; ++q) {
            s.x += sy[q][tid].x;
            s.y += sy[q][tid].y;
        }
        const int mo = mbase + tid;
        if (real_only) {
            out[mo] = s.x;
        } else {
            reinterpret_cast<float2*>(out)[mo] = s;
        }
    }
}

extern "C" void kernel_launch(void* const* d_in, const int* in_sizes, int n_in,
                              void* d_out, int out_size) {
    // Select inputs by element count (metadata order may differ):
    //   x: 2*8192*2 = 32768, f_hat: 2*64*64 = 8192
    const float* x;
    const float* f_hat;
    if (in_sizes[0] == B_DIM * M_DIM * 2) {
        x = (const float*)d_in[0];
        f_hat = (const float*)d_in[1];
    } else {
        x = (const float*)d_in[1];
        f_hat = (const float*)d_in[0];
    }

    float* out = (float*)d_out;
    const int real_only = (out_size == B_DIM * M_DIM) ? 1 : 0;

    ndft_kernel<<<B_DIM * BLOCKS_PER_B, TPB>>>(x, f_hat, out, real_only);
}

// round 16
// speedup vs baseline: 1.1628x; 1.1628x over previous
#include <cuda_runtime.h>
#include <cuda_bf16.h>

// NDFT type-2, conjugate-pair symmetry over k1 (f_hat real):
//   pair +-t: f[t]e^{-ip} + f[-t]e^{+ip} = fs*cos(p) - i*fd*sin(p)
//   t=0: fs=f (fd killed by sin(0)=0); t=32 (k1=-32): fs=f, fd=-f; t=33: pad.
// Radix on k2: k2 = 16a + c - 32.
// Block: 256 thr = 8 warps = (a, t-half h), 32 points.
// Lane = (p in [0,16), c-half ch); each lane owns points p and p+16.
// NEW: per-block shared table cstab[t][p] = (cos,sin)(2*pi*x1[p]*t) built once
// (dedups twiddle work across a-warps; hot loop has ZERO twiddle math).
// (cos,sin) pair loads as ONE b64 (LDS.64) feeding packed fma.rn.f32x2:
//   acc(P,Q) += (fs,fd) * (cos,sin). 22 instr per t-row.

#define B_DIM 2
#define M_DIM 8192
#define N1 64
#define N2 64
#define K_TOT (N1 * N2)
#define TPB 256
#define PTS 32
#define BLOCKS_PER_B (M_DIM / PTS)           // 256
#define TROWS 34                             // t = 0..32 + zero pad
#define ROWS_PW 17

#define PI_F     3.14159265358979f
#define TWO_PI_F 6.28318530717959f

typedef unsigned long long ull;

#define FMA2(d, a, b, c) \
    asm("fma.rn.f32x2 %0, %1, %2, %3;" : "=l"(d) : "l"(a), "l"(b), "l"(c))
#define UNPACK2(lo, hi, s) do { unsigned int _l, _h; \
    asm("mov.b64 {%0, %1}, %2;" : "=r"(_l), "=r"(_h) : "l"(s)); \
    (lo) = __uint_as_float(_l); (hi) = __uint_as_float(_h); } while (0)

__global__ __launch_bounds__(TPB, 4) void ndft_kernel(
    const float* __restrict__ x,      // [B, M, 2]
    const float* __restrict__ f_hat,  // [B, 64, 64]
    float* __restrict__ out,
    const int real_only)
{
    __shared__ __align__(16) float sfd[TROWS * 128];   // (fs,fd) interleaved
    __shared__ __align__(8) float2 cstab[TROWS * PTS]; // (cos,sin)[t][p]
    __shared__ float2 sy[16][PTS];                     // partials per point

    const int b    = blockIdx.x / BLOCKS_PER_B;
    const int mblk = blockIdx.x % BLOCKS_PER_B;
    const int tid  = threadIdx.x;
    const int w    = tid >> 5;
    const int lane = tid & 31;
    const int a    = w & 3;                  // k2 radix digit
    const int h    = w >> 2;                 // t-half
    const int p    = lane & 15;              // first point; second = p + 16
    const int ch   = lane >> 4;              // c-half: c = 8*ch + j
    const int mbase = b * M_DIM + mblk * PTS;

    // ---- build fs/fd interleaved: sfd[t*128 + c64*2] = (fs, fd) ----
    {
        const float* fb = f_hat + b * K_TOT;
        for (int idx = tid; idx < TROWS * 16; idx += TPB) {
            const int t = idx >> 4;
            const int g = idx & 15;
            float4 fp = make_float4(0.f, 0.f, 0.f, 0.f);
            float4 fm = make_float4(0.f, 0.f, 0.f, 0.f);
            if (t >= 1 && t <= 31)
                fp = *reinterpret_cast<const float4*>(fb + (32 + t) * N2 + g * 4);
            if (t <= 32)
                fm = *reinterpret_cast<const float4*>(fb + (32 - t) * N2 + g * 4);
            float4* dst = reinterpret_cast<float4*>(sfd + t * 128 + g * 8);
            dst[0] = make_float4(fp.x + fm.x, fp.x - fm.x, fp.y + fm.y, fp.y - fm.y);
            dst[1] = make_float4(fp.z + fm.z, fp.z - fm.z, fp.w + fm.w, fp.w - fm.w);
        }
    }

    // ---- build cos/sin table: cstab[t*32 + p] = cis(2*pi*x1[p]*t) ----
    {
        for (int idx = tid; idx < TROWS * PTS; idx += TPB) {
            const int t   = idx >> 5;
            const int pp  = idx & 31;
            const float x1p = x[(mbase + pp) * 2];
            float s, c;
            __sincosf(TWO_PI_F * x1p * (float)t, &s, &c);
            cstab[idx] = make_float2(c, s);
        }
    }

    const float x20 = x[(mbase + p) * 2 + 1];
    const float x21 = x[(mbase + p + 16) * 2 + 1];
    __syncthreads();

    // packed accumulators: accK[j] = (P, Q) for point K, local c = 8*ch + j
    ull acc0[8], acc1[8];
    #pragma unroll
    for (int j = 0; j < 8; ++j) { acc0[j] = 0ull; acc1[j] = 0ull; }

    // this lane's f slice: 4 x 16B per row, at a*128B + ch*64B
    const ulonglong2* fsd = reinterpret_cast<const ulonglong2*>(
        sfd + (h * ROWS_PW) * 128 + a * 32 + ch * 16);
    // this lane's cs pointers (2 points), stride 32 float2 per row
    const ull* cs0p = reinterpret_cast<const ull*>(cstab + (h * ROWS_PW) * PTS + p);
    const ull* cs1p = cs0p + 16;

    #pragma unroll
    for (int t = 0; t < ROWS_PW; ++t) {
        const ull cs0 = cs0p[t * PTS];   // (cos,sin) point p   — LDS.64
        const ull cs1 = cs1p[t * PTS];   // (cos,sin) point p+16

        const ulonglong2 v0 = fsd[0];    // (fs,fd) pairs c = 8ch+0..3
        const ulonglong2 v1 = fsd[1];
        const ulonglong2 v2 = fsd[2];    // c = 8ch+4..7
        const ulonglong2 v3 = fsd[3];

        FMA2(acc0[0], v0.x, cs0, acc0[0]);
        FMA2(acc1[0], v0.x, cs1, acc1[0]);
        FMA2(acc0[1], v0.y, cs0, acc0[1]);
        FMA2(acc1[1], v0.y, cs1, acc1[1]);
        FMA2(acc0[2], v1.x, cs0, acc0[2]);
        FMA2(acc1[2], v1.x, cs1, acc1[2]);
        FMA2(acc0[3], v1.y, cs0, acc0[3]);
        FMA2(acc1[3], v1.y, cs1, acc1[3]);
        FMA2(acc0[4], v2.x, cs0, acc0[4]);
        FMA2(acc1[4], v2.x, cs1, acc1[4]);
        FMA2(acc0[5], v2.y, cs0, acc0[5]);
        FMA2(acc1[5], v2.y, cs1, acc1[5]);
        FMA2(acc0[6], v3.x, cs0, acc0[6]);
        FMA2(acc1[6], v3.x, cs1, acc1[6]);
        FMA2(acc0[7], v3.y, cs0, acc0[7]);
        FMA2(acc1[7], v3.y, cs1, acc1[7]);

        fsd += 32;                       // next t row (128 floats)
    }

    // ---- tails (per point): T = sum_j w2^{8ch+j}(P_j - i Q_j); y = C_a*T ----
    #pragma unroll
    for (int k = 0; k < 2; ++k) {
        const float x2k = k ? x21 : x20;
        const ull* acc = k ? acc1 : acc0;

        float w2r, w2i;                // w2 = cis(-2*pi*x2)
        __sincosf(-TWO_PI_F * x2k, &w2i, &w2r);
        float Cr, Ci;                  // C_a = cis(-2*pi*(16a-32)*x2)
        __sincosf((64.0f - 32.0f * (float)a) * PI_F * x2k, &Ci, &Cr);
        float fr, fi;                  // E2f anchor = cis(-2*pi*8*ch*x2)
        if (ch == 0) { fr = 1.0f; fi = 0.0f; }
        else        __sincosf(-16.0f * PI_F * x2k, &fi, &fr);

        float Tr = 0.0f, Ti = 0.0f;
        #pragma unroll
        for (int j = 0; j < 8; ++j) {
            float P, Q;
            UNPACK2(P, Q, acc[j]);
            Tr += fr * P + fi * Q;
            Ti += fi * P - fr * Q;
            const float tt = fr * w2r - fi * w2i;
            fi = fr * w2i + fi * w2r;
            fr = tt;
        }
        const float yr = Cr * Tr - Ci * Ti;
        const float yi = Cr * Ti + Ci * Tr;

        sy[w * 2 + ch][p + 16 * k] = make_float2(yr, yi);
    }
    __syncthreads();

    // ---- reduction: 16 partials per point ----
    if (tid < PTS) {
        float2 s = sy[0][tid];
        #pragma unroll
        for (int q = 1; q < 16; ++q) {
            s.x += sy[q][tid].x;
            s.y += sy[q][tid].y;
        }
        const int mo = mbase + tid;
        if (real_only) {
            out[mo] = s.x;
        } else {
            reinterpret_cast<float2*>(out)[mo] = s;
        }
    }
}

extern "C" void kernel_launch(void* const* d_in, const int* in_sizes, int n_in,
                              void* d_out, int out_size) {
    // Select inputs by element count (metadata order may differ):
    //   x: 2*8192*2 = 32768, f_hat: 2*64*64 = 8192
    const float* x;
    const float* f_hat;
    if (in_sizes[0] == B_DIM * M_DIM * 2) {
        x = (const float*)d_in[0];
        f_hat = (const float*)d_in[1];
    } else {
        x = (const float*)d_in[1];
        f_hat = (const float*)d_in[0];
    }

    float* out = (float*)d_out;
    const int real_only = (out_size == B_DIM * M_DIM) ? 1 : 0;

    ndft_kernel<<<B_DIM * BLOCKS_PER_B, TPB>>>(x, f_hat, out, real_only);
}